// round 16
// baseline (speedup 1.0000x reference)
#include <cuda_runtime.h>
#include <cuda_fp16.h>
#include <mma.h>
using namespace nvcuda;

#define CCH 64
#define HH 120
#define WW 120
#define NBOX 4096
#define NPIX (HH*WW)
#define NPART 150      // g_part rows

__device__ __half g_fm_h[NPIX * CCH];       // fp16 HWC feature map
__device__ float  g_part[NPART * CCH];      // per-block channel partial sums

// padded fp16 weights (conflict-free ldm)
__device__ __half g_w1h[64 * 136];
__device__ __half g_w2h[128 * 72];
__device__ __half g_p1h[256 * 136];
__device__ __half g_p2h[128 * 72];

// ---- cp.async helpers ----
__device__ __forceinline__ void cp16(void* d, const void* s) {
    unsigned u = (unsigned)__cvta_generic_to_shared(d);
    asm volatile("cp.async.cg.shared.global [%0], [%1], 16;" :: "r"(u), "l"(s));
}
__device__ __forceinline__ void cp16ca(void* d, const void* s) {
    unsigned u = (unsigned)__cvta_generic_to_shared(d);
    asm volatile("cp.async.ca.shared.global [%0], [%1], 16;" :: "r"(u), "l"(s));
}
__device__ __forceinline__ void cp4(void* d, const void* s) {
    unsigned u = (unsigned)__cvta_generic_to_shared(d);
    asm volatile("cp.async.ca.shared.global [%0], [%1], 4;" :: "r"(u), "l"(s));
}

// ---------------------------------------------------------------- PRE: transpose (blocks 0..149, 3 tiles each) + weight convert (150..213)
__global__ void k_pre(const float* __restrict__ fm,
                      const float* __restrict__ w1, const float* __restrict__ w2,
                      const float* __restrict__ p1, const float* __restrict__ p2) {
    __shared__ float s[64][33];
    int tx = threadIdx.x, ty = threadIdx.y;          // (32, 8)
    int t = ty * 32 + tx;

    if (blockIdx.x >= 150) {
        int tid = (blockIdx.x - 150) * 256 + t;
        const int nt = 64 * 256;
        for (int i = tid; i < 8192; i += nt)  g_w1h[(i >> 7) * 136 + (i & 127)] = __float2half_rn(w1[i]);
        for (int i = tid; i < 8192; i += nt)  g_w2h[(i >> 6) * 72  + (i & 63)]  = __float2half_rn(w2[i]);
        for (int i = tid; i < 32768; i += nt) g_p1h[(i >> 7) * 136 + (i & 127)] = __float2half_rn(p1[i]);
        for (int i = tid; i < 8192; i += nt)  g_p2h[(i >> 6) * 72  + (i & 63)]  = __float2half_rn(p2[i]);
        return;
    }

    int c = t >> 2, q = t & 3;
    float vsum = 0.f;
    for (int it = 0; it < 3; it++) {
        int pix0 = (blockIdx.x * 3 + it) * 32;
        #pragma unroll
        for (int cc = ty; cc < 64; cc += 8)
            cp4(&s[cc][tx], &fm[cc * NPIX + pix0 + tx]);
        asm volatile("cp.async.commit_group;");
        asm volatile("cp.async.wait_group 0;");
        __syncthreads();

        int p = t >> 3;
        int c0 = (t & 7) * 8;
        __half h[8];
        #pragma unroll
        for (int k = 0; k < 8; k++) h[k] = __float2half_rn(s[c0 + k][p]);
        *reinterpret_cast<uint4*>(&g_fm_h[(pix0 + p) * 64 + c0]) = *reinterpret_cast<uint4*>(h);

        float v = 0.f;
        #pragma unroll
        for (int j = 0; j < 8; j++) v += s[c][q * 8 + j];
        vsum += v;
        __syncthreads();
    }
    vsum += __shfl_xor_sync(0xffffffffu, vsum, 1);
    vsum += __shfl_xor_sync(0xffffffffu, vsum, 2);
    if (q == 0) g_part[blockIdx.x * 64 + c] = vsum;
}

// ---- tensor-core pool for one scale: warp-autonomous GEMV via m8n32k16 ----
template<int R, int SROW>
__device__ __forceinline__ void pool_scale_mma(
    float cx, float cy, float bw2, float bh2,
    char* stage, __half* Atile, int lane, __half* ahrow)
{
    constexpr int CNT = 4 * R * R;
    constexpr int T = (CNT + 15) / 16;
    int lnrow = lane >> 1, sub = lane & 1;
    const char* fmbase = (const char*)g_fm_h;

    wmma::fragment<wmma::accumulator, 8, 32, 16, float> acc0, acc1;
    wmma::fill_fragment(acc0, 0.f);
    wmma::fill_fragment(acc1, 0.f);

    for (int tile = 0; tile < T; tile++) {
        int g = tile * 16 + lnrow;
        int corner = g / (R * R); corner = min(corner, 3);
        int j = g - corner * (R * R); j = min(j, R * R - 1);
        int sy = j / R, sx = j - sy * R;
        bool valid = (tile * 16 + lnrow) < CNT;

        float invr = 1.f / (float)R;
        float liny = (2.f * sy + 1.f) * invr - 1.f;
        float linx = (2.f * sx + 1.f) * invr - 1.f;
        float gy = cy + bh2 * liny;
        float gx = cx + bw2 * linx;
        float iy = ((gy + 1.f) * (float)HH - 1.f) * 0.5f;
        float ix = ((gx + 1.f) * (float)WW - 1.f) * 0.5f;
        float y0f = floorf(iy), x0f = floorf(ix);
        float wy1 = iy - y0f, wx1 = ix - x0f;
        int xi = (int)x0f + (corner & 1);
        int yi = (int)y0f + (corner >> 1);
        float wx = (corner & 1) ? wx1 : 1.f - wx1;
        float wy = (corner >> 1) ? wy1 : 1.f - wy1;
        float v = (xi >= 0 && xi < WW && yi >= 0 && yi < HH && valid) ? 1.f : 0.f;
        int xc = min(max(xi, 0), WW - 1);
        int yc = min(max(yi, 0), HH - 1);
        float w = wx * wy * v;

        const char* src = fmbase + (yc * WW + xc) * 128 + sub * 64;
        char* dst = stage + lnrow * 144 + sub * 64;
        cp16ca(dst,      src);
        cp16ca(dst + 16, src + 16);
        cp16ca(dst + 32, src + 32);
        cp16ca(dst + 48, src + 48);
        if (sub == 0) Atile[lnrow] = __float2half_rn(w);   // A[0][k]; rows 1..7 stay 0
        asm volatile("cp.async.commit_group;");
        asm volatile("cp.async.wait_group 0;");
        __syncwarp();

        wmma::fragment<wmma::matrix_a, 8, 32, 16, __half, wmma::row_major> af;
        wmma::fragment<wmma::matrix_b, 8, 32, 16, __half, wmma::row_major> bf0, bf1;
        wmma::load_matrix_sync(af, Atile, 16);
        wmma::load_matrix_sync(bf0, (__half*)stage, 72);
        wmma::load_matrix_sync(bf1, (__half*)stage + 32, 72);
        wmma::mma_sync(acc0, af, bf0, acc0);
        wmma::mma_sync(acc1, af, bf1, acc1);
        __syncwarp();   // stage reused next tile
    }

    float* sc = (float*)stage;                 // 2 x (8x32 f32, ldm 32) = 2048B <= 2304
    wmma::store_matrix_sync(sc,       acc0, 32, wmma::mem_row_major);
    wmma::store_matrix_sync(sc + 256, acc1, 32, wmma::mem_row_major);
    __syncwarp();
    const float scale = 1.f / (float)(R * R);
    ahrow[lane]      = __float2half_rn(sc[lane] * scale);
    ahrow[32 + lane] = __float2half_rn(sc[256 + lane] * scale);
    __syncwarp();
}

// ---------------------------------------------------------------- MEGA (1024 threads, 128 blocks x 32 boxes)
#define OFF_W1H 0
#define OFF_W2H 17408
#define OFF_P2H 35840
#define OFF_BSH 54272
#define OFF_GHS 55808
#define OFF_SEG2 55936
#define OFF_REGION 82048
#define OFF_FBUF (OFF_REGION + 69632)
#define SMEM_MEGA 202368

__global__ void __launch_bounds__(1024, 1)
k_mega(const float* __restrict__ boxes,
       const float* __restrict__ w1, const float* __restrict__ b1,
       const float* __restrict__ w2, const float* __restrict__ b2,
       const float* __restrict__ pb1, const float* __restrict__ pb2,
       float* __restrict__ out) {
    extern __shared__ char smem[];
    __half* w1h = (__half*)(smem + OFF_W1H);
    __half* w2h = (__half*)(smem + OFF_W2H);
    __half* p1h = (__half*)(smem + OFF_REGION);
    __half* p2h = (__half*)(smem + OFF_P2H);
    float*  bsh = (float*)(smem + OFF_BSH);
    __half* ghs = (__half*)(smem + OFF_GHS);

    int t = threadIdx.x;
    int warp = t >> 5;
    int box0 = blockIdx.x * 32;

    // ---- group A: w1h/w2h/p2h/bsh fills (p1h deferred until after pool)
    for (int i = t; i < 1088; i += 1024) cp16((uint4*)w1h + i, (const uint4*)g_w1h + i);
    for (int i = t; i < 1152; i += 1024) cp16((uint4*)w2h + i, (const uint4*)g_w2h + i);
    for (int i = t; i < 1152; i += 1024) cp16((uint4*)p2h + i, (const uint4*)g_p2h + i);
    if (t < 32)                cp16((uint4*)bsh + t,             (const uint4*)b1  + t);
    else if (t < 48)           cp16((uint4*)bsh + 32 + (t - 32), (const uint4*)b2  + (t - 32));
    else if (t >= 64 && t < 96)  cp16((uint4*)bsh + 48 + (t - 64), (const uint4*)pb1 + (t - 64));
    else if (t >= 96 && t < 112) cp16((uint4*)bsh + 80 + (t - 96), (const uint4*)pb2 + (t - 96));
    asm volatile("cp.async.commit_group;");

    // ---- global-branch head (fp32, per-block redundant; scratch in SEG2)
    {
        float* psum = (float*)(smem + OFF_SEG2);            // 1024 fl
        float* gs   = (float*)(smem + OFF_SEG2) + 1024;     // 64
        float* red  = (float*)(smem + OFF_SEG2) + 1088;     // 1024
        float* hs   = (float*)(smem + OFF_SEG2) + 2112;     // 128

        {
            int c = t & 63, g = t >> 6;                     // 16 groups
            float a = 0.f;
            for (int bb = g; bb < NPART; bb += 16) a += g_part[bb * 64 + c];
            psum[t] = a;
        }
        __syncthreads();
        if (t < 64) {
            float s = 0.f;
            #pragma unroll
            for (int q = 0; q < 16; q++) s += psum[t + 64 * q];
            gs[t] = s * (1.0f / (float)NPIX);
        }
        __syncthreads();
        {   // layer 1: 128 neurons x 8 threads
            int n = t >> 3, k0 = (t & 7) * 8;
            float acc = 0.f;
            #pragma unroll
            for (int k = 0; k < 8; k++) acc = fmaf(gs[k0 + k], w1[(k0 + k) * 128 + n], acc);
            red[t] = acc;
        }
        __syncthreads();
        if (t < 128) {
            float s = 0.f;
            #pragma unroll
            for (int q = 0; q < 8; q++) s += red[t * 8 + q];
            hs[t] = fmaxf(s + b1[t], 0.f);
        }
        __syncthreads();
        {   // layer 2: 64 neurons x 16 threads
            int n = t >> 4, k0 = (t & 15) * 8;
            float acc = 0.f;
            #pragma unroll
            for (int k = 0; k < 8; k++) acc = fmaf(hs[k0 + k], w2[(k0 + k) * 64 + n], acc);
            red[t] = acc;
        }
        __syncthreads();
        if (t < 64) {
            float s = 0.f;
            #pragma unroll
            for (int q = 0; q < 16; q++) s += red[t * 16 + q];
            ghs[t] = __float2half_rn(fmaxf(s + b2[t], 0.f));
        }
        __syncthreads();   // SEG2 scratch dead; pool may now write Ah
    }

    // ---- pool (tensor-core): warp = box; cp.async.ca gather + wmma m8n32k16
    __half* Ah = (__half*)(smem + OFF_SEG2);              // 96 x 72 halves
    {
        int lane = t & 31;
        char*   stage = smem + OFF_REGION + warp * 2304;               // 16 rows x 144B
        __half* Atile = (__half*)(smem + OFF_REGION + 73728 + warp * 256);  // 8x16 h
        ((uint2*)Atile)[lane] = make_uint2(0u, 0u);       // zero all of A
        __syncwarp();

        int box = box0 + warp;
        float x1 = boxes[box * 4 + 0] * (2.0f / 960.0f) - 1.0f;
        float y1 = boxes[box * 4 + 1] * (2.0f / 960.0f) - 1.0f;
        float x2 = boxes[box * 4 + 2] * (2.0f / 960.0f) - 1.0f;
        float y2 = boxes[box * 4 + 3] * (2.0f / 960.0f) - 1.0f;
        float cx = 0.5f * (x1 + x2), cy = 0.5f * (y1 + y2);
        float bw2 = 0.5f * fmaxf(x2 - x1, 1e-6f);
        float bh2 = 0.5f * fmaxf(y2 - y1, 1e-6f);

        pool_scale_mma<3, 0>(cx, cy, bw2, bh2, stage, Atile, lane, Ah + (0 * 32 + warp) * 72);
        pool_scale_mma<7, 1>(cx, cy, bw2, bh2, stage, Atile, lane, Ah + (1 * 32 + warp) * 72);
        pool_scale_mma<11, 2>(cx, cy, bw2, bh2, stage, Atile, lane, Ah + (2 * 32 + warp) * 72);
    }

    __syncthreads();   // pool done; REGION dead

    // ---- group B: p1h fill (lands during GEMM1/2)
    for (int i = t; i < 4352; i += 1024) cp16((uint4*)p1h + i, (const uint4*)g_p1h + i);
    asm volatile("cp.async.commit_group;");
    asm volatile("cp.async.wait_group 1;");   // everything except B done
    __syncthreads();

    // ---- GEMM1: Ah[96x64] @ w1h[64x128] -> h1f[96x132]
    float* h1f = (float*)(smem + OFF_FBUF);
    for (int tt = warp; tt < 48; tt += 32) {
        int mt = tt >> 3, nt = tt & 7;
        wmma::fragment<wmma::accumulator, 16, 16, 16, float> cf;
        wmma::fill_fragment(cf, 0.f);
        #pragma unroll
        for (int k = 0; k < 4; k++) {
            wmma::fragment<wmma::matrix_a, 16, 16, 16, __half, wmma::row_major> af;
            wmma::fragment<wmma::matrix_b, 16, 16, 16, __half, wmma::row_major> bf;
            wmma::load_matrix_sync(af, Ah + mt * 16 * 72 + k * 16, 72);
            wmma::load_matrix_sync(bf, w1h + k * 16 * 136 + nt * 16, 136);
            wmma::mma_sync(cf, af, bf, cf);
        }
        wmma::store_matrix_sync(h1f + mt * 16 * 132 + nt * 16, cf, 132, wmma::mem_row_major);
    }
    __syncthreads();

    // ---- bias + relu -> h1h[96x136] (paired)
    __half* h1h = (__half*)(smem + OFF_SEG2);
    for (int i = t; i < 96 * 64; i += 1024) {
        int r = i >> 6, c2 = (i & 63) << 1;
        float v0 = fmaxf(h1f[r * 132 + c2]     + bsh[c2],     0.f);
        float v1 = fmaxf(h1f[r * 132 + c2 + 1] + bsh[c2 + 1], 0.f);
        *reinterpret_cast<__half2*>(&h1h[r * 136 + c2]) = __floats2half2_rn(v0, v1);
    }
    __syncthreads();

    // ---- GEMM2: h1h[96x128] @ w2h[128x64] -> c2f[96x68]
    float* c2f = (float*)(smem + OFF_FBUF);
    if (warp < 24) {
        int mt = warp >> 2, nt = warp & 3;
        wmma::fragment<wmma::accumulator, 16, 16, 16, float> cf;
        wmma::fill_fragment(cf, 0.f);
        #pragma unroll
        for (int k = 0; k < 8; k++) {
            wmma::fragment<wmma::matrix_a, 16, 16, 16, __half, wmma::row_major> af;
            wmma::fragment<wmma::matrix_b, 16, 16, 16, __half, wmma::row_major> bf;
            wmma::load_matrix_sync(af, h1h + mt * 16 * 136 + k * 16, 136);
            wmma::load_matrix_sync(bf, w2h + k * 16 * 72 + nt * 16, 72);
            wmma::mma_sync(cf, af, bf, cf);
        }
        wmma::store_matrix_sync(c2f + mt * 16 * 68 + nt * 16, cf, 68, wmma::mem_row_major);
    }
    __syncthreads();

    // ---- build concat xh[32x264] (paired)
    __half* xh = (__half*)(smem + OFF_SEG2);
    for (int i = t; i < 96 * 32; i += 1024) {
        int r = i >> 5, c2 = (i & 31) << 1;
        int s = r >> 5, lb = r & 31;
        float v0 = fmaxf(c2f[r * 68 + c2]     + bsh[128 + c2],     0.f);
        float v1 = fmaxf(c2f[r * 68 + c2 + 1] + bsh[128 + c2 + 1], 0.f);
        *reinterpret_cast<__half2*>(&xh[lb * 264 + s * 64 + c2]) = __floats2half2_rn(v0, v1);
    }
    for (int i = t; i < 32 * 32; i += 1024) {
        int lb = i >> 5, c2 = (i & 31) << 1;
        *reinterpret_cast<__half2*>(&xh[lb * 264 + 192 + c2]) =
            *reinterpret_cast<const __half2*>(&ghs[c2]);
    }
    asm volatile("cp.async.wait_group 0;");   // p1h landed
    __syncthreads();

    // ---- GEMM3: xh[32x256] @ p1h[256x128] -> h2f[32x132]
    float* h2f = (float*)(smem + OFF_FBUF);
    if (warp < 16) {
        int mt = warp >> 3, nt = warp & 7;
        wmma::fragment<wmma::accumulator, 16, 16, 16, float> cf;
        wmma::fill_fragment(cf, 0.f);
        #pragma unroll
        for (int k = 0; k < 16; k++) {
            wmma::fragment<wmma::matrix_a, 16, 16, 16, __half, wmma::row_major> af;
            wmma::fragment<wmma::matrix_b, 16, 16, 16, __half, wmma::row_major> bf;
            wmma::load_matrix_sync(af, xh + mt * 16 * 264 + k * 16, 264);
            wmma::load_matrix_sync(bf, p1h + k * 16 * 136 + nt * 16, 136);
            wmma::mma_sync(cf, af, bf, cf);
        }
        wmma::store_matrix_sync(h2f + mt * 16 * 132 + nt * 16, cf, 132, wmma::mem_row_major);
    }
    __syncthreads();

    // ---- bias + relu -> h2h[32x136] (paired)
    __half* h2h = (__half*)(smem + OFF_SEG2);
    for (int i = t; i < 32 * 64; i += 1024) {
        int r = i >> 6, c2 = (i & 63) << 1;
        float v0 = fmaxf(h2f[r * 132 + c2]     + bsh[192 + c2],     0.f);
        float v1 = fmaxf(h2f[r * 132 + c2 + 1] + bsh[192 + c2 + 1], 0.f);
        *reinterpret_cast<__half2*>(&h2h[r * 136 + c2]) = __floats2half2_rn(v0, v1);
    }
    __syncthreads();

    // ---- GEMM4: h2h[32x128] @ p2h[128x64] -> c4f[32x68]
    float* c4f = (float*)(smem + OFF_FBUF);
    if (warp < 8) {
        int mt = warp >> 2, nt = warp & 3;
        wmma::fragment<wmma::accumulator, 16, 16, 16, float> cf;
        wmma::fill_fragment(cf, 0.f);
        #pragma unroll
        for (int k = 0; k < 8; k++) {
            wmma::fragment<wmma::matrix_a, 16, 16, 16, __half, wmma::row_major> af;
            wmma::fragment<wmma::matrix_b, 16, 16, 16, __half, wmma::row_major> bf;
            wmma::load_matrix_sync(af, h2h + mt * 16 * 136 + k * 16, 136);
            wmma::load_matrix_sync(bf, p2h + k * 16 * 72 + nt * 16, 72);
            wmma::mma_sync(cf, af, bf, cf);
        }
        wmma::store_matrix_sync(c4f + mt * 16 * 68 + nt * 16, cf, 68, wmma::mem_row_major);
    }
    __syncthreads();

    // ---- bias + relu -> out (paired float2 stores)
    for (int i = t; i < 32 * 32; i += 1024) {
        int r = i >> 5, c2 = (i & 31) << 1;
        float2 v;
        v.x = fmaxf(c4f[r * 68 + c2]     + bsh[320 + c2],     0.f);
        v.y = fmaxf(c4f[r * 68 + c2 + 1] + bsh[320 + c2 + 1], 0.f);
        *reinterpret_cast<float2*>(&out[(box0 + r) * 64 + c2]) = v;
    }
}

extern "C" void kernel_launch(void* const* d_in, const int* in_sizes, int n_in,
                              void* d_out, int out_size) {
    const float* fm    = (const float*)d_in[0];
    const float* boxes = (const float*)d_in[1];
    const float* w1    = (const float*)d_in[2];
    const float* b1    = (const float*)d_in[3];
    const float* w2    = (const float*)d_in[4];
    const float* b2    = (const float*)d_in[5];
    const float* p1    = (const float*)d_in[6];
    const float* pb1   = (const float*)d_in[7];
    const float* p2    = (const float*)d_in[8];
    const float* pb2   = (const float*)d_in[9];
    float* out = (float*)d_out;

    cudaFuncSetAttribute(k_mega, cudaFuncAttributeMaxDynamicSharedMemorySize, SMEM_MEGA);

    k_pre<<<214, dim3(32, 8)>>>(fm, w1, w2, p1, p2);
    k_mega<<<128, 1024, SMEM_MEGA>>>(boxes, w1, b1, w2, b2, pb1, pb2, out);
}

// round 17
// speedup vs baseline: 2.2801x; 2.2801x over previous
#include <cuda_runtime.h>
#include <cuda_fp16.h>
#include <mma.h>
using namespace nvcuda;

#define CCH 64
#define HH 120
#define WW 120
#define NBOX 4096
#define NPIX (HH*WW)
#define NSAMP 179      // 9 + 49 + 121
#define NPART 150      // g_part rows

__device__ __half g_fm_h[NPIX * CCH];       // fp16 HWC feature map
__device__ float  g_part[NPART * CCH];      // per-block channel partial sums

// padded fp16 weights (conflict-free ldm)
__device__ __half g_w1h[64 * 136];
__device__ __half g_w2h[128 * 72];
__device__ __half g_p1h[256 * 136];
__device__ __half g_p2h[128 * 72];

// ---- cp.async helpers ----
__device__ __forceinline__ void cp16(void* d, const void* s) {
    unsigned u = (unsigned)__cvta_generic_to_shared(d);
    asm volatile("cp.async.cg.shared.global [%0], [%1], 16;" :: "r"(u), "l"(s));
}
__device__ __forceinline__ void cp4(void* d, const void* s) {
    unsigned u = (unsigned)__cvta_generic_to_shared(d);
    asm volatile("cp.async.ca.shared.global [%0], [%1], 4;" :: "r"(u), "l"(s));
}

// ---------------------------------------------------------------- PRE: transpose (blocks 0..149, 3 tiles each) + weight convert (150..213)
__global__ void k_pre(const float* __restrict__ fm,
                      const float* __restrict__ w1, const float* __restrict__ w2,
                      const float* __restrict__ p1, const float* __restrict__ p2) {
    __shared__ float s[64][33];
    int tx = threadIdx.x, ty = threadIdx.y;          // (32, 8)
    int t = ty * 32 + tx;

    if (blockIdx.x >= 150) {
        int tid = (blockIdx.x - 150) * 256 + t;
        const int nt = 64 * 256;
        for (int i = tid; i < 8192; i += nt)  g_w1h[(i >> 7) * 136 + (i & 127)] = __float2half_rn(w1[i]);
        for (int i = tid; i < 8192; i += nt)  g_w2h[(i >> 6) * 72  + (i & 63)]  = __float2half_rn(w2[i]);
        for (int i = tid; i < 32768; i += nt) g_p1h[(i >> 7) * 136 + (i & 127)] = __float2half_rn(p1[i]);
        for (int i = tid; i < 8192; i += nt)  g_p2h[(i >> 6) * 72  + (i & 63)]  = __float2half_rn(p2[i]);
        return;
    }

    int c = t >> 2, q = t & 3;
    float vsum = 0.f;
    for (int it = 0; it < 3; it++) {
        int pix0 = (blockIdx.x * 3 + it) * 32;
        #pragma unroll
        for (int cc = ty; cc < 64; cc += 8)
            cp4(&s[cc][tx], &fm[cc * NPIX + pix0 + tx]);
        asm volatile("cp.async.commit_group;");
        asm volatile("cp.async.wait_group 0;");
        __syncthreads();

        int p = t >> 3;
        int c0 = (t & 7) * 8;
        __half h[8];
        #pragma unroll
        for (int k = 0; k < 8; k++) h[k] = __float2half_rn(s[c0 + k][p]);
        *reinterpret_cast<uint4*>(&g_fm_h[(pix0 + p) * 64 + c0]) = *reinterpret_cast<uint4*>(h);

        float v = 0.f;
        #pragma unroll
        for (int j = 0; j < 8; j++) v += s[c][q * 8 + j];
        vsum += v;
        __syncthreads();
    }
    vsum += __shfl_xor_sync(0xffffffffu, vsum, 1);
    vsum += __shfl_xor_sync(0xffffffffu, vsum, 2);
    if (q == 0) g_part[blockIdx.x * 64 + c] = vsum;
}

// ---------------------------------------------------------------- MEGA (1024 threads, 128 blocks x 32 boxes)
// smem layout (bytes):
//   w1h @0 (17408) | w2h @17408 (18432) | p2h @35840 (18432) | bsh @54272 (1536) | ghs @55808 (128)
//   SEG2 @55936 (26112): gh scratch -> Ah 96x72h -> h1h 96x136h -> xh 32x264h -> h2h 32x136h
//   REGION @82048 (120320):
//     pool phase: meta 16 x 5728 (91648) + sred 16 x 768 (12288) + lintab (1432)
//     gemm phase: p1h @+0 (69632), FBUF @+69632 (h1f 96x132f / c2f / h2f / c4f)
#define OFF_W1H 0
#define OFF_W2H 17408
#define OFF_P2H 35840
#define OFF_BSH 54272
#define OFF_GHS 55808
#define OFF_SEG2 55936
#define OFF_REGION 82048
#define OFF_LINTAB (OFF_REGION + 103936)
#define OFF_FBUF (OFF_REGION + 69632)
#define SMEM_MEGA 202368

__global__ void __launch_bounds__(1024, 1)
k_mega(const float* __restrict__ boxes,
       const float* __restrict__ w1, const float* __restrict__ b1,
       const float* __restrict__ w2, const float* __restrict__ b2,
       const float* __restrict__ pb1, const float* __restrict__ pb2,
       float* __restrict__ out) {
    extern __shared__ char smem[];
    __half* w1h = (__half*)(smem + OFF_W1H);
    __half* w2h = (__half*)(smem + OFF_W2H);
    __half* p1h = (__half*)(smem + OFF_REGION);
    __half* p2h = (__half*)(smem + OFF_P2H);
    float*  bsh = (float*)(smem + OFF_BSH);
    __half* ghs = (__half*)(smem + OFF_GHS);
    float2* lintab = (float2*)(smem + OFF_LINTAB);

    int t = threadIdx.x;
    int warp = t >> 5;
    int box0 = blockIdx.x * 32;

    // ---- group A: w1h/w2h/p2h/bsh fills (p1h deferred until after pool)
    for (int i = t; i < 1088; i += 1024) cp16((uint4*)w1h + i, (const uint4*)g_w1h + i);
    for (int i = t; i < 1152; i += 1024) cp16((uint4*)w2h + i, (const uint4*)g_w2h + i);
    for (int i = t; i < 1152; i += 1024) cp16((uint4*)p2h + i, (const uint4*)g_p2h + i);
    if (t < 32)                cp16((uint4*)bsh + t,             (const uint4*)b1  + t);
    else if (t < 48)           cp16((uint4*)bsh + 32 + (t - 32), (const uint4*)b2  + (t - 32));
    else if (t >= 64 && t < 96)  cp16((uint4*)bsh + 48 + (t - 64), (const uint4*)pb1 + (t - 64));
    else if (t >= 96 && t < 112) cp16((uint4*)bsh + 80 + (t - 96), (const uint4*)pb2 + (t - 96));
    asm volatile("cp.async.commit_group;");

    // ---- box-independent sample grid table (covered by gh-phase barriers)
    if (t < NSAMP) {
        int i = t, r, j;
        if (i < 9)       { r = 3;  j = i; }
        else if (i < 58) { r = 7;  j = i - 9; }
        else             { r = 11; j = i - 58; }
        int sy = j / r, sx = j - sy * r;
        float invr = 1.0f / (float)r;
        lintab[i] = make_float2((2.0f * sx + 1.0f) * invr - 1.0f,
                                (2.0f * sy + 1.0f) * invr - 1.0f);
    }

    // ---- global-branch head (fp32, per-block redundant; scratch in SEG2)
    {
        float* psum = (float*)(smem + OFF_SEG2);            // 1024 fl
        float* gs   = (float*)(smem + OFF_SEG2) + 1024;     // 64
        float* red  = (float*)(smem + OFF_SEG2) + 1088;     // 1024
        float* hs   = (float*)(smem + OFF_SEG2) + 2112;     // 128

        {
            int c = t & 63, g = t >> 6;                     // 16 groups
            float a = 0.f;
            for (int bb = g; bb < NPART; bb += 16) a += g_part[bb * 64 + c];
            psum[t] = a;
        }
        __syncthreads();
        if (t < 64) {
            float s = 0.f;
            #pragma unroll
            for (int q = 0; q < 16; q++) s += psum[t + 64 * q];
            gs[t] = s * (1.0f / (float)NPIX);
        }
        __syncthreads();
        {   // layer 1: 128 neurons x 8 threads
            int n = t >> 3, k0 = (t & 7) * 8;
            float acc = 0.f;
            #pragma unroll
            for (int k = 0; k < 8; k++) acc = fmaf(gs[k0 + k], w1[(k0 + k) * 128 + n], acc);
            red[t] = acc;
        }
        __syncthreads();
        if (t < 128) {
            float s = 0.f;
            #pragma unroll
            for (int q = 0; q < 8; q++) s += red[t * 8 + q];
            hs[t] = fmaxf(s + b1[t], 0.f);
        }
        __syncthreads();
        {   // layer 2: 64 neurons x 16 threads
            int n = t >> 4, k0 = (t & 15) * 8;
            float acc = 0.f;
            #pragma unroll
            for (int k = 0; k < 8; k++) acc = fmaf(hs[k0 + k], w2[(k0 + k) * 64 + n], acc);
            red[t] = acc;
        }
        __syncthreads();
        if (t < 64) {
            float s = 0.f;
            #pragma unroll
            for (int q = 0; q < 16; q++) s += red[t * 16 + q];
            ghs[t] = __float2half_rn(fmaxf(s + b2[t], 0.f));
        }
        __syncthreads();   // SEG2 scratch dead; pool may now write Ah
    }

    // ---- pool: 16 slots x 64 thr; thread = (corner, parity, 8-ch chunk); LDG.128 fp16
    __half* Ah = (__half*)(smem + OFF_SEG2);              // 96 x 72 halves
    {
        int slot = t >> 6;                                // 0..15
        int tid = t & 63;
        int chunk = tid & 7;                              // 8 channels each
        int par   = (tid >> 3) & 1;                       // even/odd samples
        int corner = tid >> 4;                            // 0..3
        char*   meta = smem + OFF_REGION + slot * 5728;   // [4][179] x {int off, float w}
        float4* sred = (float4*)(smem + OFF_REGION + 91648) + slot * 48;   // [3][8][2] float4
        const char* fmb = (const char*)g_fm_h + chunk * 16;
        int barid = 1 + (slot & 7);                       // two slots share one barrier, count 128

        for (int q = 0; q < 2; q++) {
            int lb = q * 16 + slot;
            int box = box0 + lb;

            float x1 = boxes[box * 4 + 0] * (2.0f / 960.0f) - 1.0f;
            float y1 = boxes[box * 4 + 1] * (2.0f / 960.0f) - 1.0f;
            float x2 = boxes[box * 4 + 2] * (2.0f / 960.0f) - 1.0f;
            float y2 = boxes[box * 4 + 3] * (2.0f / 960.0f) - 1.0f;
            float cx = 0.5f * (x1 + x2), cy = 0.5f * (y1 + y2);
            float bw2 = 0.5f * fmaxf(x2 - x1, 1e-6f);
            float bh2 = 0.5f * fmaxf(y2 - y1, 1e-6f);

            for (int i = tid; i < NSAMP; i += 64) {
                float2 lin = lintab[i];
                float gy = cy + bh2 * lin.y;
                float gx = cx + bw2 * lin.x;
                float iy = ((gy + 1.0f) * (float)HH - 1.0f) * 0.5f;
                float ix = ((gx + 1.0f) * (float)WW - 1.0f) * 0.5f;
                float y0f = floorf(iy), x0f = floorf(ix);
                float wy1 = iy - y0f, wx1 = ix - x0f;
                int y0 = (int)y0f, x0 = (int)x0f;
                int y1i = y0 + 1, x1i = x0 + 1;
                float vx0 = (x0 >= 0 && x0 < WW) ? 1.f : 0.f;
                float vx1 = (x1i >= 0 && x1i < WW) ? 1.f : 0.f;
                float vy0 = (y0 >= 0 && y0 < HH) ? 1.f : 0.f;
                float vy1 = (y1i >= 0 && y1i < HH) ? 1.f : 0.f;
                int x0c = min(max(x0, 0), WW - 1);
                int x1c = min(max(x1i, 0), WW - 1);
                int y0c = min(max(y0, 0), HH - 1);
                int y1c = min(max(y1i, 0), HH - 1);
                ((int2*)(meta + 0 * 1432))[i] = make_int2((y0c * WW + x0c) * 128,
                    __float_as_int((1.f - wx1) * (1.f - wy1) * vx0 * vy0));
                ((int2*)(meta + 1 * 1432))[i] = make_int2((y0c * WW + x1c) * 128,
                    __float_as_int(wx1 * (1.f - wy1) * vx1 * vy0));
                ((int2*)(meta + 2 * 1432))[i] = make_int2((y1c * WW + x0c) * 128,
                    __float_as_int((1.f - wx1) * wy1 * vx0 * vy1));
                ((int2*)(meta + 3 * 1432))[i] = make_int2((y1c * WW + x1c) * 128,
                    __float_as_int(wx1 * wy1 * vx1 * vy1));
            }
            asm volatile("bar.sync %0, 128;" :: "r"(barid) : "memory");

            const int2* mp = (const int2*)(meta + corner * 1432);
            float4 aA0 = make_float4(0.f, 0.f, 0.f, 0.f);
            float4 aB0 = aA0, aA1 = aA0, aB1 = aA0, aA2 = aA0, aB2 = aA0;

#define SAMPLE(AA, AB, I) { \
            int2 pw = mp[I]; \
            uint4 u = *reinterpret_cast<const uint4*>(fmb + pw.x); \
            float w = __int_as_float(pw.y); \
            float2 f0 = __half22float2(*reinterpret_cast<__half2*>(&u.x)); \
            float2 f1 = __half22float2(*reinterpret_cast<__half2*>(&u.y)); \
            float2 f2 = __half22float2(*reinterpret_cast<__half2*>(&u.z)); \
            float2 f3 = __half22float2(*reinterpret_cast<__half2*>(&u.w)); \
            AA.x = fmaf(f0.x, w, AA.x); AA.y = fmaf(f0.y, w, AA.y); \
            AA.z = fmaf(f1.x, w, AA.z); AA.w = fmaf(f1.y, w, AA.w); \
            AB.x = fmaf(f2.x, w, AB.x); AB.y = fmaf(f2.y, w, AB.y); \
            AB.z = fmaf(f3.x, w, AB.z); AB.w = fmaf(f3.y, w, AB.w); }

            #pragma unroll 2
            for (int i = par; i < 9; i += 2)          SAMPLE(aA0, aB0, i)
            #pragma unroll 4
            for (int i = 9 + par; i < 58; i += 2)     SAMPLE(aA1, aB1, i)
            #pragma unroll 6
            for (int i = 58 + par; i < NSAMP; i += 2) SAMPLE(aA2, aB2, i)
#undef SAMPLE

            // reduce parity (xor 8) then corner bit0 (xor 16); corner bit1 via smem
#define RED(V, M) { \
            V.x += __shfl_xor_sync(0xffffffffu, V.x, M); \
            V.y += __shfl_xor_sync(0xffffffffu, V.y, M); \
            V.z += __shfl_xor_sync(0xffffffffu, V.z, M); \
            V.w += __shfl_xor_sync(0xffffffffu, V.w, M); }
            RED(aA0, 8) RED(aB0, 8) RED(aA1, 8) RED(aB1, 8) RED(aA2, 8) RED(aB2, 8)
            RED(aA0, 16) RED(aB0, 16) RED(aA1, 16) RED(aB1, 16) RED(aA2, 16) RED(aB2, 16)
#undef RED

            if (tid >= 32 && tid < 40) {     // corners 2+3 merged partial
                sred[(0 * 8 + chunk) * 2 + 0] = aA0;
                sred[(0 * 8 + chunk) * 2 + 1] = aB0;
                sred[(1 * 8 + chunk) * 2 + 0] = aA1;
                sred[(1 * 8 + chunk) * 2 + 1] = aB1;
                sred[(2 * 8 + chunk) * 2 + 0] = aA2;
                sred[(2 * 8 + chunk) * 2 + 1] = aB2;
            }
            asm volatile("bar.sync %0, 128;" :: "r"(barid) : "memory");
            if (tid < 8) {
                float4 rA0 = sred[(0 * 8 + chunk) * 2 + 0], rB0 = sred[(0 * 8 + chunk) * 2 + 1];
                float4 rA1 = sred[(1 * 8 + chunk) * 2 + 0], rB1 = sred[(1 * 8 + chunk) * 2 + 1];
                float4 rA2 = sred[(2 * 8 + chunk) * 2 + 0], rB2 = sred[(2 * 8 + chunk) * 2 + 1];
                const float sc0 = 1.f / 9.f, sc1 = 1.f / 49.f, sc2 = 1.f / 121.f;
                __half2 h0, h1, h2, h3;
                uint4 pv;
                h0 = __floats2half2_rn((aA0.x + rA0.x) * sc0, (aA0.y + rA0.y) * sc0);
                h1 = __floats2half2_rn((aA0.z + rA0.z) * sc0, (aA0.w + rA0.w) * sc0);
                h2 = __floats2half2_rn((aB0.x + rB0.x) * sc0, (aB0.y + rB0.y) * sc0);
                h3 = __floats2half2_rn((aB0.z + rB0.z) * sc0, (aB0.w + rB0.w) * sc0);
                pv = make_uint4(*(unsigned*)&h0, *(unsigned*)&h1, *(unsigned*)&h2, *(unsigned*)&h3);
                *reinterpret_cast<uint4*>(&Ah[(0 * 32 + lb) * 72 + chunk * 8]) = pv;
                h0 = __floats2half2_rn((aA1.x + rA1.x) * sc1, (aA1.y + rA1.y) * sc1);
                h1 = __floats2half2_rn((aA1.z + rA1.z) * sc1, (aA1.w + rA1.w) * sc1);
                h2 = __floats2half2_rn((aB1.x + rB1.x) * sc1, (aB1.y + rB1.y) * sc1);
                h3 = __floats2half2_rn((aB1.z + rB1.z) * sc1, (aB1.w + rB1.w) * sc1);
                pv = make_uint4(*(unsigned*)&h0, *(unsigned*)&h1, *(unsigned*)&h2, *(unsigned*)&h3);
                *reinterpret_cast<uint4*>(&Ah[(1 * 32 + lb) * 72 + chunk * 8]) = pv;
                h0 = __floats2half2_rn((aA2.x + rA2.x) * sc2, (aA2.y + rA2.y) * sc2);
                h1 = __floats2half2_rn((aA2.z + rA2.z) * sc2, (aA2.w + rA2.w) * sc2);
                h2 = __floats2half2_rn((aB2.x + rB2.x) * sc2, (aB2.y + rB2.y) * sc2);
                h3 = __floats2half2_rn((aB2.z + rB2.z) * sc2, (aB2.w + rB2.w) * sc2);
                pv = make_uint4(*(unsigned*)&h0, *(unsigned*)&h1, *(unsigned*)&h2, *(unsigned*)&h3);
                *reinterpret_cast<uint4*>(&Ah[(2 * 32 + lb) * 72 + chunk * 8]) = pv;
            }
        }
    }

    __syncthreads();   // pool done; meta region dead

    // ---- group B: p1h fill (lands during GEMM1/2)
    for (int i = t; i < 4352; i += 1024) cp16((uint4*)p1h + i, (const uint4*)g_p1h + i);
    asm volatile("cp.async.commit_group;");
    asm volatile("cp.async.wait_group 1;");   // group A (w1h/w2h/p2h/bsh) done
    __syncthreads();

    // ---- GEMM1: Ah[96x64] @ w1h[64x128] -> h1f[96x132]
    float* h1f = (float*)(smem + OFF_FBUF);
    for (int tt = warp; tt < 48; tt += 32) {
        int mt = tt >> 3, nt = tt & 7;
        wmma::fragment<wmma::accumulator, 16, 16, 16, float> cf;
        wmma::fill_fragment(cf, 0.f);
        #pragma unroll
        for (int k = 0; k < 4; k++) {
            wmma::fragment<wmma::matrix_a, 16, 16, 16, __half, wmma::row_major> af;
            wmma::fragment<wmma::matrix_b, 16, 16, 16, __half, wmma::row_major> bf;
            wmma::load_matrix_sync(af, Ah + mt * 16 * 72 + k * 16, 72);
            wmma::load_matrix_sync(bf, w1h + k * 16 * 136 + nt * 16, 136);
            wmma::mma_sync(cf, af, bf, cf);
        }
        wmma::store_matrix_sync(h1f + mt * 16 * 132 + nt * 16, cf, 132, wmma::mem_row_major);
    }
    __syncthreads();

    // ---- bias + relu -> h1h[96x136] (paired)
    __half* h1h = (__half*)(smem + OFF_SEG2);
    for (int i = t; i < 96 * 64; i += 1024) {
        int r = i >> 6, c2 = (i & 63) << 1;
        float v0 = fmaxf(h1f[r * 132 + c2]     + bsh[c2],     0.f);
        float v1 = fmaxf(h1f[r * 132 + c2 + 1] + bsh[c2 + 1], 0.f);
        *reinterpret_cast<__half2*>(&h1h[r * 136 + c2]) = __floats2half2_rn(v0, v1);
    }
    __syncthreads();

    // ---- GEMM2: h1h[96x128] @ w2h[128x64] -> c2f[96x68]
    float* c2f = (float*)(smem + OFF_FBUF);
    if (warp < 24) {
        int mt = warp >> 2, nt = warp & 3;
        wmma::fragment<wmma::accumulator, 16, 16, 16, float> cf;
        wmma::fill_fragment(cf, 0.f);
        #pragma unroll
        for (int k = 0; k < 8; k++) {
            wmma::fragment<wmma::matrix_a, 16, 16, 16, __half, wmma::row_major> af;
            wmma::fragment<wmma::matrix_b, 16, 16, 16, __half, wmma::row_major> bf;
            wmma::load_matrix_sync(af, h1h + mt * 16 * 136 + k * 16, 136);
            wmma::load_matrix_sync(bf, w2h + k * 16 * 72 + nt * 16, 72);
            wmma::mma_sync(cf, af, bf, cf);
        }
        wmma::store_matrix_sync(c2f + mt * 16 * 68 + nt * 16, cf, 68, wmma::mem_row_major);
    }
    __syncthreads();

    // ---- build concat xh[32x264] (paired)
    __half* xh = (__half*)(smem + OFF_SEG2);
    for (int i = t; i < 96 * 32; i += 1024) {
        int r = i >> 5, c2 = (i & 31) << 1;
        int s = r >> 5, lb = r & 31;
        float v0 = fmaxf(c2f[r * 68 + c2]     + bsh[128 + c2],     0.f);
        float v1 = fmaxf(c2f[r * 68 + c2 + 1] + bsh[128 + c2 + 1], 0.f);
        *reinterpret_cast<__half2*>(&xh[lb * 264 + s * 64 + c2]) = __floats2half2_rn(v0, v1);
    }
    for (int i = t; i < 32 * 32; i += 1024) {
        int lb = i >> 5, c2 = (i & 31) << 1;
        *reinterpret_cast<__half2*>(&xh[lb * 264 + 192 + c2]) =
            *reinterpret_cast<const __half2*>(&ghs[c2]);
    }
    asm volatile("cp.async.wait_group 0;");   // p1h landed
    __syncthreads();

    // ---- GEMM3: xh[32x256] @ p1h[256x128] -> h2f[32x132]
    float* h2f = (float*)(smem + OFF_FBUF);
    if (warp < 16) {
        int mt = warp >> 3, nt = warp & 7;
        wmma::fragment<wmma::accumulator, 16, 16, 16, float> cf;
        wmma::fill_fragment(cf, 0.f);
        #pragma unroll
        for (int k = 0; k < 16; k++) {
            wmma::fragment<wmma::matrix_a, 16, 16, 16, __half, wmma::row_major> af;
            wmma::fragment<wmma::matrix_b, 16, 16, 16, __half, wmma::row_major> bf;
            wmma::load_matrix_sync(af, xh + mt * 16 * 264 + k * 16, 264);
            wmma::load_matrix_sync(bf, p1h + k * 16 * 136 + nt * 16, 136);
            wmma::mma_sync(cf, af, bf, cf);
        }
        wmma::store_matrix_sync(h2f + mt * 16 * 132 + nt * 16, cf, 132, wmma::mem_row_major);
    }
    __syncthreads();

    // ---- bias + relu -> h2h[32x136] (paired)
    __half* h2h = (__half*)(smem + OFF_SEG2);
    for (int i = t; i < 32 * 64; i += 1024) {
        int r = i >> 6, c2 = (i & 63) << 1;
        float v0 = fmaxf(h2f[r * 132 + c2]     + bsh[192 + c2],     0.f);
        float v1 = fmaxf(h2f[r * 132 + c2 + 1] + bsh[192 + c2 + 1], 0.f);
        *reinterpret_cast<__half2*>(&h2h[r * 136 + c2]) = __floats2half2_rn(v0, v1);
    }
    __syncthreads();

    // ---- GEMM4: h2h[32x128] @ p2h[128x64] -> c4f[32x68]
    float* c4f = (float*)(smem + OFF_FBUF);
    if (warp < 8) {
        int mt = warp >> 2, nt = warp & 3;
        wmma::fragment<wmma::accumulator, 16, 16, 16, float> cf;
        wmma::fill_fragment(cf, 0.f);
        #pragma unroll
        for (int k = 0; k < 8; k++) {
            wmma::fragment<wmma::matrix_a, 16, 16, 16, __half, wmma::row_major> af;
            wmma::fragment<wmma::matrix_b, 16, 16, 16, __half, wmma::row_major> bf;
            wmma::load_matrix_sync(af, h2h + mt * 16 * 136 + k * 16, 136);
            wmma::load_matrix_sync(bf, p2h + k * 16 * 72 + nt * 16, 72);
            wmma::mma_sync(cf, af, bf, cf);
        }
        wmma::store_matrix_sync(c4f + mt * 16 * 68 + nt * 16, cf, 68, wmma::mem_row_major);
    }
    __syncthreads();

    // ---- bias + relu -> out (paired float2 stores)
    for (int i = t; i < 32 * 32; i += 1024) {
        int r = i >> 5, c2 = (i & 31) << 1;
        float2 v;
        v.x = fmaxf(c4f[r * 68 + c2]     + bsh[320 + c2],     0.f);
        v.y = fmaxf(c4f[r * 68 + c2 + 1] + bsh[320 + c2 + 1], 0.f);
        *reinterpret_cast<float2*>(&out[(box0 + r) * 64 + c2]) = v;
    }
}

extern "C" void kernel_launch(void* const* d_in, const int* in_sizes, int n_in,
                              void* d_out, int out_size) {
    const float* fm    = (const float*)d_in[0];
    const float* boxes = (const float*)d_in[1];
    const float* w1    = (const float*)d_in[2];
    const float* b1    = (const float*)d_in[3];
    const float* w2    = (const float*)d_in[4];
    const float* b2    = (const float*)d_in[5];
    const float* p1    = (const float*)d_in[6];
    const float* pb1   = (const float*)d_in[7];
    const float* p2    = (const float*)d_in[8];
    const float* pb2   = (const float*)d_in[9];
    float* out = (float*)d_out;

    cudaFuncSetAttribute(k_mega, cudaFuncAttributeMaxDynamicSharedMemorySize, SMEM_MEGA);

    k_pre<<<214, dim3(32, 8)>>>(fm, w1, w2, p1, p2);
    k_mega<<<128, 1024, SMEM_MEGA>>>(boxes, w1, b1, w2, b2, pb1, pb2, out);
}